// round 1
// baseline (speedup 1.0000x reference)
#include <cuda_runtime.h>

#define NN 100000
#define EE 1600000
#define TPB 256

static inline int cdiv(long long a, int b) { return (int)((a + b - 1) / b); }

// ---------------- device scratch (static, no allocations) ----------------
__device__ __align__(16) float g_xw[(size_t)NN * 88];   // [xw(40) | skip(40) | asrc(4) | adst(4)]
__device__ __align__(16) float g_h[(size_t)NN * 40];    // hidden activations
__device__ __align__(16) float g_z[(size_t)NN * 280];   // layer3 features: z(240) | h2 skip(40)
__device__ __align__(16) float g_agg[(size_t)NN * 40];  // layers 1/2 aggregation
__device__ float g_asrc[(size_t)NN * 6];
__device__ float g_adst[(size_t)NN * 6];
__device__ unsigned g_mx[(size_t)NN * 6];               // encoded float max
__device__ float g_den[(size_t)NN * 6];
__device__ float g_ew[(size_t)EE * 6];                  // per-edge exp weights
__device__ float g_w1e[50 * 88];
__device__ float g_w2e[40 * 88];
__device__ float g_w3e[280 * 121];
__device__ float g_bc1[40], g_bc2[40], g_bc3[121];
__device__ float g_vs3[240], g_vd3[240];

// ---------------- helpers ----------------
__device__ __forceinline__ unsigned f2o(float f) {
    unsigned u = __float_as_uint(f);
    return (u & 0x80000000u) ? ~u : (u | 0x80000000u);
}
__device__ __forceinline__ float o2f(unsigned u) {
    return (u & 0x80000000u) ? __uint_as_float(u ^ 0x80000000u) : __uint_as_float(~u);
}
__device__ __forceinline__ float lrelu(float x) { return x > 0.f ? x : 0.2f * x; }

__device__ __forceinline__ void red4(float* p, float4 v) {
    asm volatile("red.global.add.v4.f32 [%0], {%1,%2,%3,%4};"
                 :: "l"(p), "f"(v.x), "f"(v.y), "f"(v.z), "f"(v.w) : "memory");
}

// ---------------- weight repack ----------------
__global__ void k_repack12(const float* __restrict__ W, const float* __restrict__ lw,
                           const float* __restrict__ as_, const float* __restrict__ ad_,
                           const float* __restrict__ b, const float* __restrict__ lb,
                           float* we, float* bc, int K) {
    int t = blockIdx.x * blockDim.x + threadIdx.x;
    if (t >= K * 88) return;
    int k = t / 88, j = t % 88;
    float v;
    if (j < 40) v = W[k * 40 + j];
    else if (j < 80) v = lw[k * 40 + (j - 40)];
    else if (j < 84) {
        int h = j - 80; float a = 0.f;
        for (int d = 0; d < 10; d++) a += W[k * 40 + h * 10 + d] * as_[h * 10 + d];
        v = a;
    } else {
        int h = j - 84; float a = 0.f;
        for (int d = 0; d < 10; d++) a += W[k * 40 + h * 10 + d] * ad_[h * 10 + d];
        v = a;
    }
    we[t] = v;
    if (k == 0 && j < 40) bc[j] = b[j] + lb[j];
}

__global__ void k_repack3(const float* __restrict__ W3, const float* __restrict__ lw3,
                          const float* __restrict__ b3, const float* __restrict__ lb3,
                          float* we, float* bc) {
    int t = blockIdx.x * blockDim.x + threadIdx.x;
    if (t >= 280 * 121) return;
    int r = t / 121, c = t % 121;
    float v;
    if (r < 240) { int h = r / 40, k = r % 40; v = W3[k * 726 + h * 121 + c]; }
    else v = lw3[(r - 240) * 121 + c];
    we[t] = v;
    if (r == 0) bc[c] = b3[c] + lb3[c];
}

__global__ void k_vsd3(const float* __restrict__ W3, const float* __restrict__ as3,
                       const float* __restrict__ ad3, float* vs, float* vd) {
    int t = blockIdx.x * blockDim.x + threadIdx.x;
    if (t >= 480) return;
    int side = t / 240, idx = t % 240, h = idx / 40, k = idx % 40;
    const float* att = side ? ad3 : as3;
    float a = 0.f;
    for (int c = 0; c < 121; c++) a += W3[k * 726 + h * 121 + c] * att[h * 121 + c];
    (side ? vd : vs)[idx] = a;
}

// ---------------- generic fp32 GEMM: C[M,NC] = A[M,K] @ B[K,NC] (+bias) ----------------
__global__ __launch_bounds__(256) void k_gemm(const float* __restrict__ A, int lda,
                                              const float* __restrict__ B, int ldb,
                                              float* __restrict__ C, int ldc,
                                              int M, int K, int NC,
                                              const float* __restrict__ bias) {
    __shared__ float As[16][65];
    __shared__ float Bs[16][65];
    int bm = blockIdx.x * 64, bn = blockIdx.y * 64;
    int tid = threadIdx.x;
    int tx = tid & 15, ty = tid >> 4;
    float acc[4][4] = {};
    for (int k0 = 0; k0 < K; k0 += 16) {
        for (int i = tid; i < 64 * 16; i += 256) {
            int m = i >> 4, kk = i & 15;
            int gm = bm + m, gk = k0 + kk;
            As[kk][m] = (gm < M && gk < K) ? A[gm * lda + gk] : 0.f;
        }
        for (int i = tid; i < 16 * 64; i += 256) {
            int kk = i >> 6, nn2 = i & 63;
            int gk = k0 + kk, gn = bn + nn2;
            Bs[kk][nn2] = (gk < K && gn < NC) ? B[gk * ldb + gn] : 0.f;
        }
        __syncthreads();
#pragma unroll
        for (int kk = 0; kk < 16; kk++) {
            float a[4], b[4];
#pragma unroll
            for (int i = 0; i < 4; i++) a[i] = As[kk][ty * 4 + i];
#pragma unroll
            for (int j = 0; j < 4; j++) b[j] = Bs[kk][tx * 4 + j];
#pragma unroll
            for (int i = 0; i < 4; i++)
#pragma unroll
                for (int j = 0; j < 4; j++) acc[i][j] += a[i] * b[j];
        }
        __syncthreads();
    }
#pragma unroll
    for (int i = 0; i < 4; i++) {
        int r = bm + ty * 4 + i;
        if (r >= M) continue;
#pragma unroll
        for (int j = 0; j < 4; j++) {
            int cc = bn + tx * 4 + j;
            if (cc >= NC) continue;
            C[r * ldc + cc] = acc[i][j] + (bias ? bias[cc] : 0.f);
        }
    }
}

// ---------------- attention passes ----------------
__global__ void k_initmax(const float* __restrict__ as_, int lds,
                          const float* __restrict__ ad_, int ldd,
                          int H, unsigned* mx, int n) {
    int t = blockIdx.x * blockDim.x + threadIdx.x;
    if (t >= n * H) return;
    int node = t / H, h = t - node * H;
    float s = lrelu(as_[node * lds + h] + ad_[node * ldd + h]);
    mx[t] = f2o(s);
}

__global__ void k_edgemax(const int* __restrict__ src, const int* __restrict__ dst,
                          const float* __restrict__ as_, int lds,
                          const float* __restrict__ ad_, int ldd,
                          int H, unsigned* mx, int E) {
    int t = blockIdx.x * blockDim.x + threadIdx.x;
    if (t >= E * H) return;
    int e = t / H, h = t - e * H;
    int s = src[e], d = dst[e];
    float sc = lrelu(as_[s * lds + h] + ad_[d * ldd + h]);
    atomicMax(&mx[d * H + h], f2o(sc));
}

// self-loop contribution: init agg/z and denom
__global__ void k_selfinit(const float* __restrict__ feat, int ldf,
                           const float* __restrict__ as_, int lds,
                           const float* __restrict__ ad_, int ldd,
                           int H, int D, const unsigned* __restrict__ mx,
                           float* out, int ldo, float* den, int n) {
    int C = H * D;
    int t = blockIdx.x * blockDim.x + threadIdx.x;
    if (t >= n * C) return;
    int node = t / C, c = t - node * C, h = c / D;
    float sc = lrelu(as_[node * lds + h] + ad_[node * ldd + h]);
    float w = __expf(sc - o2f(mx[node * H + h]));
    out[(long long)node * ldo + c] = w * feat[(long long)node * ldf + (c % 40)];
    if (c == h * D) den[node * H + h] = w;
}

__global__ void k_edgew(const int* __restrict__ src, const int* __restrict__ dst,
                        const float* __restrict__ as_, int lds,
                        const float* __restrict__ ad_, int ldd,
                        int H, const unsigned* __restrict__ mx,
                        float* ew, float* den, int E) {
    int t = blockIdx.x * blockDim.x + threadIdx.x;
    if (t >= E * H) return;
    int e = t / H, h = t - e * H;
    int s = src[e], d = dst[e];
    float sc = lrelu(as_[s * lds + h] + ad_[d * ldd + h]);
    float w = __expf(sc - o2f(mx[d * H + h]));
    ew[t] = w;
    atomicAdd(&den[d * H + h], w);
}

__global__ void k_edgeagg(const int* __restrict__ src, const int* __restrict__ dst,
                          const float* __restrict__ ew, const float* __restrict__ feat,
                          int ldf, int H, int D, float* out, int ldo, int C, int E) {
    int G = C >> 2;
    long long t = (long long)blockIdx.x * blockDim.x + threadIdx.x;
    if (t >= (long long)E * G) return;
    int e = (int)(t / G);
    int c = (int)(t - (long long)e * G) * 4;
    int s = src[e], d = dst[e];
    const float* fw = &ew[(long long)e * H];
    float4 f = *(const float4*)(feat + (long long)s * ldf + (c % 40));
    float4 v;
    v.x = f.x * fw[c / D];
    v.y = f.y * fw[(c + 1) / D];
    v.z = f.z * fw[(c + 2) / D];
    v.w = f.w * fw[(c + 3) / D];
    red4(out + (long long)d * ldo + c, v);
}

// epilogue layers 1/2: agg/den + skip + bias, ELU; optionally mirror into z skip cols
__global__ void k_epi12(const float* __restrict__ agg, const float* __restrict__ xw,
                        const float* __restrict__ den, const float* __restrict__ bias,
                        float* hout, float* zout, int n) {
    int t = blockIdx.x * blockDim.x + threadIdx.x;
    if (t >= n * 40) return;
    int node = t / 40, j = t - node * 40, h = j / 10;
    float v = agg[t] / den[node * 4 + h] + xw[(long long)node * 88 + 40 + j] + bias[j];
    float e = v > 0.f ? v : (__expf(v) - 1.f);
    hout[t] = e;
    if (zout) zout[(long long)node * 280 + 240 + j] = e;
}

// layer3 attention logits via folded vectors
__global__ void k_asrc3(const float* __restrict__ h2, const float* __restrict__ vs,
                        const float* __restrict__ vd, float* as_, float* ad_, int n) {
    int t = blockIdx.x * blockDim.x + threadIdx.x;
    if (t >= n * 12) return;
    int node = t / 12, j = t - node * 12;
    const float* v = (j < 6) ? &vs[j * 40] : &vd[(j - 6) * 40];
    const float* hr = &h2[(long long)node * 40];
    float a = 0.f;
#pragma unroll
    for (int k = 0; k < 40; k++) a += hr[k] * v[k];
    if (j < 6) as_[node * 6 + j] = a;
    else ad_[node * 6 + (j - 6)] = a;
}

// scale z by 1/(6*den) (folds heads-mean + softmax normalization)
__global__ void k_scalez(float* z, const float* __restrict__ den, int n) {
    int t = blockIdx.x * blockDim.x + threadIdx.x;
    if (t >= n * 240) return;
    int node = t / 240, c = t - node * 240, h = c / 40;
    z[(long long)node * 280 + c] *= 1.f / (6.f * den[node * 6 + h]);
}

// ---------------- host ----------------
extern "C" void kernel_launch(void* const* d_in, const int* in_sizes, int n_in,
                              void* d_out, int out_size) {
    const float* x   = (const float*)d_in[0];
    const int*   ei  = (const int*)d_in[1];
    const float* W1  = (const float*)d_in[2];
    const float* as1 = (const float*)d_in[3];
    const float* ad1 = (const float*)d_in[4];
    const float* b1  = (const float*)d_in[5];
    const float* lw1 = (const float*)d_in[6];
    const float* lb1 = (const float*)d_in[7];
    const float* W2  = (const float*)d_in[8];
    const float* as2 = (const float*)d_in[9];
    const float* ad2 = (const float*)d_in[10];
    const float* b2  = (const float*)d_in[11];
    const float* lw2 = (const float*)d_in[12];
    const float* lb2 = (const float*)d_in[13];
    const float* W3  = (const float*)d_in[14];
    const float* as3 = (const float*)d_in[15];
    const float* ad3 = (const float*)d_in[16];
    const float* b3  = (const float*)d_in[17];
    const float* lw3 = (const float*)d_in[18];
    const float* lb3 = (const float*)d_in[19];
    float* out = (float*)d_out;

    int E = in_sizes[1] / 2;
    int n = in_sizes[0] / 50;
    const int* src = ei;
    const int* dst = ei + E;

    float *xw, *h, *z, *agg, *asrc, *adst, *den, *ew;
    float *w1e, *w2e, *w3e, *bc1, *bc2, *bc3, *vs3, *vd3;
    unsigned* mx;
    cudaGetSymbolAddress((void**)&xw, g_xw);
    cudaGetSymbolAddress((void**)&h, g_h);
    cudaGetSymbolAddress((void**)&z, g_z);
    cudaGetSymbolAddress((void**)&agg, g_agg);
    cudaGetSymbolAddress((void**)&asrc, g_asrc);
    cudaGetSymbolAddress((void**)&adst, g_adst);
    cudaGetSymbolAddress((void**)&mx, g_mx);
    cudaGetSymbolAddress((void**)&den, g_den);
    cudaGetSymbolAddress((void**)&ew, g_ew);
    cudaGetSymbolAddress((void**)&w1e, g_w1e);
    cudaGetSymbolAddress((void**)&w2e, g_w2e);
    cudaGetSymbolAddress((void**)&w3e, g_w3e);
    cudaGetSymbolAddress((void**)&bc1, g_bc1);
    cudaGetSymbolAddress((void**)&bc2, g_bc2);
    cudaGetSymbolAddress((void**)&bc3, g_bc3);
    cudaGetSymbolAddress((void**)&vs3, g_vs3);
    cudaGetSymbolAddress((void**)&vd3, g_vd3);

    // weight repack
    k_repack12<<<cdiv(50 * 88, TPB), TPB>>>(W1, lw1, as1, ad1, b1, lb1, w1e, bc1, 50);
    k_repack12<<<cdiv(40 * 88, TPB), TPB>>>(W2, lw2, as2, ad2, b2, lb2, w2e, bc2, 40);
    k_repack3<<<cdiv(280 * 121, TPB), TPB>>>(W3, lw3, b3, lb3, w3e, bc3);
    k_vsd3<<<cdiv(480, TPB), TPB>>>(W3, as3, ad3, vs3, vd3);

    // ---- layer 1 (H=4, D=10, in=50) ----
    {
        dim3 g(cdiv(n, 64), cdiv(88, 64));
        k_gemm<<<g, 256>>>(x, 50, w1e, 88, xw, 88, n, 50, 88, nullptr);
        k_initmax<<<cdiv(n * 4, TPB), TPB>>>(xw + 80, 88, xw + 84, 88, 4, mx, n);
        k_edgemax<<<cdiv((long long)E * 4, TPB), TPB>>>(src, dst, xw + 80, 88, xw + 84, 88, 4, mx, E);
        k_selfinit<<<cdiv(n * 40, TPB), TPB>>>(xw, 88, xw + 80, 88, xw + 84, 88, 4, 10, mx, agg, 40, den, n);
        k_edgew<<<cdiv((long long)E * 4, TPB), TPB>>>(src, dst, xw + 80, 88, xw + 84, 88, 4, mx, ew, den, E);
        k_edgeagg<<<cdiv((long long)E * 10, TPB), TPB>>>(src, dst, ew, xw, 88, 4, 10, agg, 40, 40, E);
        k_epi12<<<cdiv(n * 40, TPB), TPB>>>(agg, xw, den, bc1, h, nullptr, n);
    }

    // ---- layer 2 (H=4, D=10, in=40) ----
    {
        dim3 g(cdiv(n, 64), cdiv(88, 64));
        k_gemm<<<g, 256>>>(h, 40, w2e, 88, xw, 88, n, 40, 88, nullptr);
        k_initmax<<<cdiv(n * 4, TPB), TPB>>>(xw + 80, 88, xw + 84, 88, 4, mx, n);
        k_edgemax<<<cdiv((long long)E * 4, TPB), TPB>>>(src, dst, xw + 80, 88, xw + 84, 88, 4, mx, E);
        k_selfinit<<<cdiv(n * 40, TPB), TPB>>>(xw, 88, xw + 80, 88, xw + 84, 88, 4, 10, mx, agg, 40, den, n);
        k_edgew<<<cdiv((long long)E * 4, TPB), TPB>>>(src, dst, xw + 80, 88, xw + 84, 88, 4, mx, ew, den, E);
        k_edgeagg<<<cdiv((long long)E * 10, TPB), TPB>>>(src, dst, ew, xw, 88, 4, 10, agg, 40, 40, E);
        k_epi12<<<cdiv(n * 40, TPB), TPB>>>(agg, xw, den, bc2, h, z, n);  // writes h2 and z skip cols
    }

    // ---- layer 3 (H=6, aggregate 40-d inputs per head, then GEMM) ----
    {
        k_asrc3<<<cdiv(n * 12, TPB), TPB>>>(h, vs3, vd3, asrc, adst, n);
        k_initmax<<<cdiv(n * 6, TPB), TPB>>>(asrc, 6, adst, 6, 6, mx, n);
        k_edgemax<<<cdiv((long long)E * 6, TPB), TPB>>>(src, dst, asrc, 6, adst, 6, 6, mx, E);
        k_selfinit<<<cdiv(n * 240, TPB), TPB>>>(h, 40, asrc, 6, adst, 6, 6, 40, mx, z, 280, den, n);
        k_edgew<<<cdiv((long long)E * 6, TPB), TPB>>>(src, dst, asrc, 6, adst, 6, 6, mx, ew, den, E);
        k_edgeagg<<<cdiv((long long)E * 60, TPB), TPB>>>(src, dst, ew, h, 40, 6, 40, z, 280, 240, E);
        k_scalez<<<cdiv(n * 240, TPB), TPB>>>(z, den, n);
        dim3 g(cdiv(n, 64), cdiv(121, 64));
        k_gemm<<<g, 256>>>(z, 280, w3e, 121, out, 121, n, 280, 121, bc3);
    }
}

// round 5
// speedup vs baseline: 1.9247x; 1.9247x over previous
#include <cuda_runtime.h>

#define NN 100000
#define EE 1600000
#define TPB 256

static inline int cdiv(long long a, int b) { return (int)((a + b - 1) / b); }

// ---------------- device scratch ----------------
__device__ __align__(16) float g_xw[(size_t)NN * 88];   // [xw(40) | skip(40) | asrc(4) | adst(4)]
__device__ __align__(16) float g_h[(size_t)NN * 40];
__device__ __align__(16) float g_z[(size_t)NN * 280];   // z(240) | h2 skip(40)
__device__ float g_asrc[(size_t)NN * 6];
__device__ float g_adst[(size_t)NN * 6];
__device__ float g_ws[(size_t)NN * 6];                  // self-loop exp weights (layer3)
__device__ float g_ew[(size_t)EE * 6];                  // per-edge exp weights (CSR order)
__device__ int g_cnt[NN], g_ptr[NN], g_cur[NN], g_bsum[128];
__device__ int g_csrc[EE], g_cdst[EE];
__device__ float g_w1e[50 * 88];
__device__ float g_w2e[40 * 88];
__device__ float g_w3e[280 * 121];
__device__ float g_bc1[40], g_bc2[40], g_bc3[121];
__device__ float g_vs3[240], g_vd3[240];

__device__ __forceinline__ float lrelu(float x) { return x > 0.f ? x : 0.2f * x; }

// ---------------- weight repack ----------------
__global__ void k_repack12(const float* __restrict__ W, const float* __restrict__ lw,
                           const float* __restrict__ as_, const float* __restrict__ ad_,
                           const float* __restrict__ b, const float* __restrict__ lb,
                           float* we, float* bc, int K) {
    int t = blockIdx.x * blockDim.x + threadIdx.x;
    if (t >= K * 88) return;
    int k = t / 88, j = t % 88;
    float v;
    if (j < 40) v = W[k * 40 + j];
    else if (j < 80) v = lw[k * 40 + (j - 40)];
    else if (j < 84) {
        int h = j - 80; float a = 0.f;
        for (int d = 0; d < 10; d++) a += W[k * 40 + h * 10 + d] * as_[h * 10 + d];
        v = a;
    } else {
        int h = j - 84; float a = 0.f;
        for (int d = 0; d < 10; d++) a += W[k * 40 + h * 10 + d] * ad_[h * 10 + d];
        v = a;
    }
    we[t] = v;
    if (k == 0 && j < 40) bc[j] = b[j] + lb[j];
}

__global__ void k_repack3(const float* __restrict__ W3, const float* __restrict__ lw3,
                          const float* __restrict__ b3, const float* __restrict__ lb3,
                          float* we, float* bc) {
    int t = blockIdx.x * blockDim.x + threadIdx.x;
    if (t >= 280 * 121) return;
    int r = t / 121, c = t % 121;
    float v;
    if (r < 240) { int h = r / 40, k = r % 40; v = W3[k * 726 + h * 121 + c]; }
    else v = lw3[(r - 240) * 121 + c];
    we[t] = v;
    if (r == 0) bc[c] = b3[c] + lb3[c];
}

__global__ void k_vsd3(const float* __restrict__ W3, const float* __restrict__ as3,
                       const float* __restrict__ ad3, float* vs, float* vd) {
    int t = blockIdx.x * blockDim.x + threadIdx.x;
    if (t >= 480) return;
    int side = t / 240, idx = t % 240, h = idx / 40, k = idx % 40;
    const float* att = side ? ad3 : as3;
    float a = 0.f;
    for (int c = 0; c < 121; c++) a += W3[k * 726 + h * 121 + c] * att[h * 121 + c];
    (side ? vd : vs)[idx] = a;
}

// ---------------- CSR build ----------------
__global__ void k_hist(const int* __restrict__ dst, int* cnt, int E) {
    int t = blockIdx.x * blockDim.x + threadIdx.x;
    if (t < E) atomicAdd(&cnt[dst[t]], 1);
}

__global__ void k_scan1(const int* __restrict__ cnt, int* ptr, int* bsum, int n) {
    __shared__ int sh[1024];
    int i = blockIdx.x * 1024 + threadIdx.x;
    int v = (i < n) ? cnt[i] : 0;
    sh[threadIdx.x] = v;
    __syncthreads();
    for (int off = 1; off < 1024; off <<= 1) {
        int t = (threadIdx.x >= off) ? sh[threadIdx.x - off] : 0;
        __syncthreads();
        sh[threadIdx.x] += t;
        __syncthreads();
    }
    if (i < n) ptr[i] = sh[threadIdx.x] - v;   // exclusive
    if (threadIdx.x == 1023) bsum[blockIdx.x] = sh[1023];
}

__global__ void k_scan2(int* bsum, int nb) {
    __shared__ int sh[128];
    int v = (threadIdx.x < nb) ? bsum[threadIdx.x] : 0;
    sh[threadIdx.x] = v;
    __syncthreads();
    for (int off = 1; off < 128; off <<= 1) {
        int t = (threadIdx.x >= off) ? sh[threadIdx.x - off] : 0;
        __syncthreads();
        sh[threadIdx.x] += t;
        __syncthreads();
    }
    if (threadIdx.x < nb) bsum[threadIdx.x] = sh[threadIdx.x] - v;
}

__global__ void k_scan3(int* ptr, int* cur, const int* __restrict__ bsum, int n) {
    int i = blockIdx.x * blockDim.x + threadIdx.x;
    if (i >= n) return;
    int p = ptr[i] + bsum[i >> 10];
    ptr[i] = p;
    cur[i] = p;
}

__global__ void k_scatter(const int* __restrict__ src, const int* __restrict__ dst,
                          int* cur, int* csrc, int* cdst, int E) {
    int t = blockIdx.x * blockDim.x + threadIdx.x;
    if (t >= E) return;
    int d = dst[t];
    int slot = atomicAdd(&cur[d], 1);
    csrc[slot] = src[t];
    cdst[slot] = d;
}

// ---------------- GEMM: C[M,NC] = A[M,K] @ B[K,NC] (+bias) ----------------
__global__ __launch_bounds__(256) void k_gemm(const float* __restrict__ A, int lda,
                                              const float* __restrict__ B, int ldb,
                                              float* __restrict__ C, int ldc,
                                              int M, int K, int NC,
                                              const float* __restrict__ bias) {
    __shared__ __align__(16) float As[16][68];
    __shared__ __align__(16) float Bs[16][68];
    int bm = blockIdx.x * 64, bn = blockIdx.y * 64;
    int tid = threadIdx.x;
    int tx = tid & 15, ty = tid >> 4;
    float acc[4][4] = {};
    for (int k0 = 0; k0 < K; k0 += 16) {
        for (int i = tid; i < 64 * 16; i += 256) {
            int m = i >> 4, kk = i & 15;
            int gm = bm + m, gk = k0 + kk;
            As[kk][m] = (gm < M && gk < K) ? A[(long long)gm * lda + gk] : 0.f;
        }
        for (int i = tid; i < 16 * 64; i += 256) {
            int kk = i >> 6, nn2 = i & 63;
            int gk = k0 + kk, gn = bn + nn2;
            Bs[kk][nn2] = (gk < K && gn < NC) ? B[gk * ldb + gn] : 0.f;
        }
        __syncthreads();
#pragma unroll
        for (int kk = 0; kk < 16; kk++) {
            float4 a = *(const float4*)&As[kk][ty * 4];
            float4 b = *(const float4*)&Bs[kk][tx * 4];
            float av[4] = {a.x, a.y, a.z, a.w};
            float bv[4] = {b.x, b.y, b.z, b.w};
#pragma unroll
            for (int i = 0; i < 4; i++)
#pragma unroll
                for (int j = 0; j < 4; j++) acc[i][j] += av[i] * bv[j];
        }
        __syncthreads();
    }
#pragma unroll
    for (int i = 0; i < 4; i++) {
        int r = bm + ty * 4 + i;
        if (r >= M) continue;
#pragma unroll
        for (int j = 0; j < 4; j++) {
            int cc = bn + tx * 4 + j;
            if (cc >= NC) continue;
            C[(long long)r * ldc + cc] = acc[i][j] + (bias ? bias[cc] : 0.f);
        }
    }
}

// ---------------- per-edge exp weights (CSR order) ----------------
__global__ void k_exp12(const int* __restrict__ csrc, const int* __restrict__ cdst,
                        const float* __restrict__ xw, float* __restrict__ ew, int E) {
    int t = blockIdx.x * blockDim.x + threadIdx.x;
    if (t >= E * 4) return;
    int slot = t >> 2, h = t & 3;
    int s = csrc[slot], d = cdst[slot];
    float sc = lrelu(xw[(long long)s * 88 + 80 + h] + xw[(long long)d * 88 + 84 + h]);
    ew[t] = __expf(sc);
}

__global__ void k_exp3(const int* __restrict__ csrc, const int* __restrict__ cdst,
                       const float* __restrict__ as_, const float* __restrict__ ad_,
                       float* __restrict__ ew, int E) {
    long long t = (long long)blockIdx.x * blockDim.x + threadIdx.x;
    if (t >= (long long)E * 6) return;
    int slot = (int)(t / 6), h = (int)(t - (long long)slot * 6);
    int s = csrc[slot], d = cdst[slot];
    float sc = lrelu(as_[s * 6 + h] + ad_[d * 6 + h]);
    ew[t] = __expf(sc);
}

// ---------------- fused aggregation layers 1/2 ----------------
// thread = (node, 4 cols). Gathers neighbors, accumulates denom locally,
// normalizes, adds skip+bias, ELU. No atomics.
__global__ __launch_bounds__(256) void k_agg12(
    const int* __restrict__ ptr, const int* __restrict__ cnt,
    const int* __restrict__ csrc, const float* __restrict__ xw,
    const float* __restrict__ ew, const float* __restrict__ bias,
    float* __restrict__ hout, float* __restrict__ zout, int n) {
    int t = blockIdx.x * blockDim.x + threadIdx.x;
    if (t >= n * 10) return;
    int node = t / 10, g = t - node * 10;
    int c0 = g * 4;
    int hlo = c0 / 10, hhi = (c0 + 3) / 10;
    bool two = (hhi != hlo);
    int hj1 = (c0 + 1) / 10, hj2 = (c0 + 2) / 10;

    const float* rowd = xw + (long long)node * 88;
    // self loop
    float wlo = __expf(lrelu(rowd[80 + hlo] + rowd[84 + hlo]));
    float whi = two ? __expf(lrelu(rowd[80 + hhi] + rowd[84 + hhi])) : wlo;
    float4 fs = *(const float4*)(rowd + c0);
    float w0 = wlo, w1 = (hj1 == hlo) ? wlo : whi, w2 = (hj2 == hlo) ? wlo : whi, w3 = whi;
    float ax = fs.x * w0, ay = fs.y * w1, az = fs.z * w2, aw = fs.w * w3;
    float dlo = wlo, dhi = whi;

    int st = ptr[node], deg = cnt[node];
    for (int k = 0; k < deg; k++) {
        int slot = st + k;
        int s = csrc[slot];
        float wl = ew[slot * 4 + hlo];
        float wh = two ? ew[slot * 4 + hhi] : wl;
        float4 f = *(const float4*)(xw + (long long)s * 88 + c0);
        ax += f.x * ((hj1 == hlo || true) ? wl : wl);  // comp0 always hlo
        ay += f.y * ((hj1 == hlo) ? wl : wh);
        az += f.z * ((hj2 == hlo) ? wl : wh);
        aw += f.w * wh;
        dlo += wl;
        dhi += wh;
    }
    float ilo = 1.f / dlo, ihi = two ? (1.f / dhi) : ilo;
    float i1 = (hj1 == hlo) ? ilo : ihi, i2 = (hj2 == hlo) ? ilo : ihi;
    float4 r;
    r.x = ax * ilo + rowd[40 + c0 + 0] + bias[c0 + 0];
    r.y = ay * i1  + rowd[40 + c0 + 1] + bias[c0 + 1];
    r.z = az * i2  + rowd[40 + c0 + 2] + bias[c0 + 2];
    r.w = aw * ihi + rowd[40 + c0 + 3] + bias[c0 + 3];
    r.x = r.x > 0.f ? r.x : (__expf(r.x) - 1.f);
    r.y = r.y > 0.f ? r.y : (__expf(r.y) - 1.f);
    r.z = r.z > 0.f ? r.z : (__expf(r.z) - 1.f);
    r.w = r.w > 0.f ? r.w : (__expf(r.w) - 1.f);
    *(float4*)(hout + (long long)node * 40 + c0) = r;
    if (zout) *(float4*)(zout + (long long)node * 280 + 240 + c0) = r;
}

// ---------------- layer 3 ----------------
__global__ void k_asrc3(const float* __restrict__ h2, const float* __restrict__ vs,
                        const float* __restrict__ vd, float* as_, float* ad_, int n) {
    int t = blockIdx.x * blockDim.x + threadIdx.x;
    if (t >= n * 12) return;
    int node = t / 12, j = t - node * 12;
    const float* v = (j < 6) ? &vs[j * 40] : &vd[(j - 6) * 40];
    const float* hr = &h2[(long long)node * 40];
    float a = 0.f;
#pragma unroll
    for (int k = 0; k < 40; k++) a += hr[k] * v[k];
    if (j < 6) as_[node * 6 + j] = a;
    else ad_[node * 6 + (j - 6)] = a;
}

__global__ void k_selfw(const float* __restrict__ as_, const float* __restrict__ ad_,
                        float* ws, int n) {
    int t = blockIdx.x * blockDim.x + threadIdx.x;
    if (t >= n * 6) return;
    ws[t] = __expf(lrelu(as_[t] + ad_[t]));
}

// thread = (node, 4 feature cols), all 6 heads in registers. One gather serves 6 heads.
__global__ __launch_bounds__(256) void k_agg3(
    const int* __restrict__ ptr, const int* __restrict__ cnt,
    const int* __restrict__ csrc, const float* __restrict__ h2,
    const float* __restrict__ ew, const float* __restrict__ ws,
    float* __restrict__ z, int n) {
    int t = blockIdx.x * blockDim.x + threadIdx.x;
    if (t >= n * 10) return;
    int node = t / 10, g = t - node * 10;
    int fc0 = g * 4;

    float den[6];
    float4 acc[6];
    float4 fself = *(const float4*)(h2 + (long long)node * 40 + fc0);
#pragma unroll
    for (int h = 0; h < 6; h++) {
        float w = ws[node * 6 + h];
        den[h] = w;
        acc[h].x = fself.x * w; acc[h].y = fself.y * w;
        acc[h].z = fself.z * w; acc[h].w = fself.w * w;
    }
    int st = ptr[node], deg = cnt[node];
    for (int k = 0; k < deg; k++) {
        int slot = st + k;
        int s = csrc[slot];
        float4 f = *(const float4*)(h2 + (long long)s * 40 + fc0);
        const float* wp = &ew[(long long)slot * 6];
#pragma unroll
        for (int h = 0; h < 6; h++) {
            float w = wp[h];
            den[h] += w;
            acc[h].x += f.x * w; acc[h].y += f.y * w;
            acc[h].z += f.z * w; acc[h].w += f.w * w;
        }
    }
#pragma unroll
    for (int h = 0; h < 6; h++) {
        float sc = 1.f / (6.f * den[h]);
        float4 r;
        r.x = acc[h].x * sc; r.y = acc[h].y * sc;
        r.z = acc[h].z * sc; r.w = acc[h].w * sc;
        *(float4*)(z + (long long)node * 280 + h * 40 + fc0) = r;
    }
}

// ---------------- host ----------------
extern "C" void kernel_launch(void* const* d_in, const int* in_sizes, int n_in,
                              void* d_out, int out_size) {
    const float* x   = (const float*)d_in[0];
    const int*   ei  = (const int*)d_in[1];
    const float* W1  = (const float*)d_in[2];
    const float* as1 = (const float*)d_in[3];
    const float* ad1 = (const float*)d_in[4];
    const float* b1  = (const float*)d_in[5];
    const float* lw1 = (const float*)d_in[6];
    const float* lb1 = (const float*)d_in[7];
    const float* W2  = (const float*)d_in[8];
    const float* as2 = (const float*)d_in[9];
    const float* ad2 = (const float*)d_in[10];
    const float* b2  = (const float*)d_in[11];
    const float* lw2 = (const float*)d_in[12];
    const float* lb2 = (const float*)d_in[13];
    const float* W3  = (const float*)d_in[14];
    const float* as3 = (const float*)d_in[15];
    const float* ad3 = (const float*)d_in[16];
    const float* b3  = (const float*)d_in[17];
    const float* lw3 = (const float*)d_in[18];
    const float* lb3 = (const float*)d_in[19];
    float* out = (float*)d_out;

    int E = in_sizes[1] / 2;
    int n = in_sizes[0] / 50;
    const int* src = ei;
    const int* dst = ei + E;

    float *xw, *h, *z, *asrc, *adst, *ws, *ew;
    float *w1e, *w2e, *w3e, *bc1, *bc2, *bc3, *vs3, *vd3;
    int *cnt, *ptr, *cur, *bsum, *csrc, *cdst;
    cudaGetSymbolAddress((void**)&xw, g_xw);
    cudaGetSymbolAddress((void**)&h, g_h);
    cudaGetSymbolAddress((void**)&z, g_z);
    cudaGetSymbolAddress((void**)&asrc, g_asrc);
    cudaGetSymbolAddress((void**)&adst, g_adst);
    cudaGetSymbolAddress((void**)&ws, g_ws);
    cudaGetSymbolAddress((void**)&ew, g_ew);
    cudaGetSymbolAddress((void**)&cnt, g_cnt);
    cudaGetSymbolAddress((void**)&ptr, g_ptr);
    cudaGetSymbolAddress((void**)&cur, g_cur);
    cudaGetSymbolAddress((void**)&bsum, g_bsum);
    cudaGetSymbolAddress((void**)&csrc, g_csrc);
    cudaGetSymbolAddress((void**)&cdst, g_cdst);
    cudaGetSymbolAddress((void**)&w1e, g_w1e);
    cudaGetSymbolAddress((void**)&w2e, g_w2e);
    cudaGetSymbolAddress((void**)&w3e, g_w3e);
    cudaGetSymbolAddress((void**)&bc1, g_bc1);
    cudaGetSymbolAddress((void**)&bc2, g_bc2);
    cudaGetSymbolAddress((void**)&bc3, g_bc3);
    cudaGetSymbolAddress((void**)&vs3, g_vs3);
    cudaGetSymbolAddress((void**)&vd3, g_vd3);

    // weight repack
    k_repack12<<<cdiv(50 * 88, TPB), TPB>>>(W1, lw1, as1, ad1, b1, lb1, w1e, bc1, 50);
    k_repack12<<<cdiv(40 * 88, TPB), TPB>>>(W2, lw2, as2, ad2, b2, lb2, w2e, bc2, 40);
    k_repack3<<<cdiv(280 * 121, TPB), TPB>>>(W3, lw3, b3, lb3, w3e, bc3);
    k_vsd3<<<cdiv(480, TPB), TPB>>>(W3, as3, ad3, vs3, vd3);

    // CSR build (shared by all 3 layers)
    cudaMemsetAsync(cnt, 0, (size_t)n * sizeof(int));
    k_hist<<<cdiv(E, TPB), TPB>>>(dst, cnt, E);
    int nb = cdiv(n, 1024);
    k_scan1<<<nb, 1024>>>(cnt, ptr, bsum, n);
    k_scan2<<<1, 128>>>(bsum, nb);
    k_scan3<<<cdiv(n, TPB), TPB>>>(ptr, cur, bsum, n);
    k_scatter<<<cdiv(E, TPB), TPB>>>(src, dst, cur, csrc, cdst, E);

    // ---- layer 1 ----
    {
        dim3 g(cdiv(n, 64), cdiv(88, 64));
        k_gemm<<<g, 256>>>(x, 50, w1e, 88, xw, 88, n, 50, 88, nullptr);
        k_exp12<<<cdiv((long long)E * 4, TPB), TPB>>>(csrc, cdst, xw, ew, E);
        k_agg12<<<cdiv(n * 10, TPB), TPB>>>(ptr, cnt, csrc, xw, ew, bc1, h, nullptr, n);
    }
    // ---- layer 2 ----
    {
        dim3 g(cdiv(n, 64), cdiv(88, 64));
        k_gemm<<<g, 256>>>(h, 40, w2e, 88, xw, 88, n, 40, 88, nullptr);
        k_exp12<<<cdiv((long long)E * 4, TPB), TPB>>>(csrc, cdst, xw, ew, E);
        k_agg12<<<cdiv(n * 10, TPB), TPB>>>(ptr, cnt, csrc, xw, ew, bc2, h, z, n);
    }
    // ---- layer 3 ----
    {
        k_asrc3<<<cdiv(n * 12, TPB), TPB>>>(h, vs3, vd3, asrc, adst, n);
        k_selfw<<<cdiv(n * 6, TPB), TPB>>>(asrc, adst, ws, n);
        k_exp3<<<cdiv((long long)E * 6, TPB), TPB>>>(csrc, cdst, asrc, adst, ew, E);
        k_agg3<<<cdiv(n * 10, TPB), TPB>>>(ptr, cnt, csrc, h, ew, ws, z, n);
        dim3 g(cdiv(n, 64), cdiv(121, 64));
        k_gemm<<<g, 256>>>(z, 280, w3e, 121, out, 121, n, 280, 121, bc3);
    }
}

// round 7
// speedup vs baseline: 3.2813x; 1.7048x over previous
#include <cuda_runtime.h>
#include <cuda_fp16.h>
#include <mma.h>
using namespace nvcuda;

#define NN 100000
#define EE 1600000
#define TPB 256

static inline int cdiv(long long a, int b) { return (int)((a + b - 1) / b); }

// ---------------- device scratch ----------------
__device__ __align__(16) float g_xw[(size_t)NN * 88];   // [xw(40) | skip(40) | asrc(4) | adst(4)]
__device__ __align__(16) float g_h[(size_t)NN * 40];
__device__ __align__(16) float g_z[(size_t)NN * 280];   // z(240) | h2 skip(40)
__device__ float g_asrc[(size_t)NN * 6];
__device__ float g_adst[(size_t)NN * 6];
__device__ float g_ws[(size_t)NN * 6];                  // self-loop exp weights (layer3)
__device__ float g_ew[(size_t)EE * 6];                  // per-edge exp weights (layer3, CSR order)
__device__ int g_cnt[NN], g_ptr[NN], g_cur[NN], g_bsum[128];
__device__ int g_csrc[EE], g_cdst[EE];
__device__ float g_w1e[50 * 88];
__device__ float g_w2e[40 * 88];
__device__ __align__(16) __half g_w3h[288 * 128];       // padded half weights for layer3 GEMM
__device__ float g_bc1[40], g_bc2[40], g_bc3[121];
__device__ float g_vs3[240], g_vd3[240];

__device__ __forceinline__ float lrelu(float x) { return x > 0.f ? x : 0.2f * x; }

// ---------------- weight repack ----------------
__global__ void k_repack12(const float* __restrict__ W, const float* __restrict__ lw,
                           const float* __restrict__ as_, const float* __restrict__ ad_,
                           const float* __restrict__ b, const float* __restrict__ lb,
                           float* we, float* bc, int K) {
    int t = blockIdx.x * blockDim.x + threadIdx.x;
    if (t >= K * 88) return;
    int k = t / 88, j = t % 88;
    float v;
    if (j < 40) v = W[k * 40 + j];
    else if (j < 80) v = lw[k * 40 + (j - 40)];
    else if (j < 84) {
        int h = j - 80; float a = 0.f;
        for (int d = 0; d < 10; d++) a += W[k * 40 + h * 10 + d] * as_[h * 10 + d];
        v = a;
    } else {
        int h = j - 84; float a = 0.f;
        for (int d = 0; d < 10; d++) a += W[k * 40 + h * 10 + d] * ad_[h * 10 + d];
        v = a;
    }
    we[t] = v;
    if (k == 0 && j < 40) bc[j] = b[j] + lb[j];
}

// layer3 weights -> half, padded to [288][128] (rows 240..279 = lw3, rest zero)
__global__ void k_repack3h(const float* __restrict__ W3, const float* __restrict__ lw3,
                           const float* __restrict__ b3, const float* __restrict__ lb3,
                           __half* wh, float* bc) {
    int t = blockIdx.x * blockDim.x + threadIdx.x;
    if (t >= 288 * 128) return;
    int r = t >> 7, c = t & 127;
    float v = 0.f;
    if (c < 121) {
        if (r < 240) { int h = r / 40, k = r % 40; v = W3[k * 726 + h * 121 + c]; }
        else if (r < 280) v = lw3[(r - 240) * 121 + c];
    }
    wh[t] = __float2half(v);
    if (r == 0 && c < 121) bc[c] = b3[c] + lb3[c];
}

__global__ void k_vsd3(const float* __restrict__ W3, const float* __restrict__ as3,
                       const float* __restrict__ ad3, float* vs, float* vd) {
    int t = blockIdx.x * blockDim.x + threadIdx.x;
    if (t >= 480) return;
    int side = t / 240, idx = t % 240, h = idx / 40, k = idx % 40;
    const float* att = side ? ad3 : as3;
    float a = 0.f;
    for (int c = 0; c < 121; c++) a += W3[k * 726 + h * 121 + c] * att[h * 121 + c];
    (side ? vd : vs)[idx] = a;
}

// ---------------- CSR build ----------------
__global__ void k_hist(const int* __restrict__ dst, int* cnt, int E) {
    int t = blockIdx.x * blockDim.x + threadIdx.x;
    if (t < E) atomicAdd(&cnt[dst[t]], 1);
}

__global__ void k_scan1(const int* __restrict__ cnt, int* ptr, int* bsum, int n) {
    __shared__ int sh[1024];
    int i = blockIdx.x * 1024 + threadIdx.x;
    int v = (i < n) ? cnt[i] : 0;
    sh[threadIdx.x] = v;
    __syncthreads();
    for (int off = 1; off < 1024; off <<= 1) {
        int t = (threadIdx.x >= off) ? sh[threadIdx.x - off] : 0;
        __syncthreads();
        sh[threadIdx.x] += t;
        __syncthreads();
    }
    if (i < n) ptr[i] = sh[threadIdx.x] - v;   // exclusive
    if (threadIdx.x == 1023) bsum[blockIdx.x] = sh[1023];
}

__global__ void k_scan2(int* bsum, int nb) {
    __shared__ int sh[128];
    int v = (threadIdx.x < nb) ? bsum[threadIdx.x] : 0;
    sh[threadIdx.x] = v;
    __syncthreads();
    for (int off = 1; off < 128; off <<= 1) {
        int t = (threadIdx.x >= off) ? sh[threadIdx.x - off] : 0;
        __syncthreads();
        sh[threadIdx.x] += t;
        __syncthreads();
    }
    if (threadIdx.x < nb) bsum[threadIdx.x] = sh[threadIdx.x] - v;
}

__global__ void k_scan3(int* ptr, int* cur, const int* __restrict__ bsum, int n) {
    int i = blockIdx.x * blockDim.x + threadIdx.x;
    if (i >= n) return;
    int p = ptr[i] + bsum[i >> 10];
    ptr[i] = p;
    cur[i] = p;
}

__global__ void k_scatter(const int* __restrict__ src, const int* __restrict__ dst,
                          int* cur, int* csrc, int* cdst, int E) {
    int t = blockIdx.x * blockDim.x + threadIdx.x;
    if (t >= E) return;
    int d = dst[t];
    int slot = atomicAdd(&cur[d], 1);
    csrc[slot] = src[t];
    cdst[slot] = d;
}

// ---------------- SIMT fp32 GEMM (layers 1/2, exact) ----------------
__global__ __launch_bounds__(256) void k_gemm(const float* __restrict__ A, int lda,
                                              const float* __restrict__ B, int ldb,
                                              float* __restrict__ C, int ldc,
                                              int M, int K, int NC,
                                              const float* __restrict__ bias) {
    __shared__ __align__(16) float As[16][68];
    __shared__ __align__(16) float Bs[16][68];
    int bm = blockIdx.x * 64, bn = blockIdx.y * 64;
    int tid = threadIdx.x;
    int tx = tid & 15, ty = tid >> 4;
    float acc[4][4] = {};
    for (int k0 = 0; k0 < K; k0 += 16) {
        for (int i = tid; i < 64 * 16; i += 256) {
            int m = i >> 4, kk = i & 15;
            int gm = bm + m, gk = k0 + kk;
            As[kk][m] = (gm < M && gk < K) ? A[(long long)gm * lda + gk] : 0.f;
        }
        for (int i = tid; i < 16 * 64; i += 256) {
            int kk = i >> 6, nn2 = i & 63;
            int gk = k0 + kk, gn = bn + nn2;
            Bs[kk][nn2] = (gk < K && gn < NC) ? B[gk * ldb + gn] : 0.f;
        }
        __syncthreads();
#pragma unroll
        for (int kk = 0; kk < 16; kk++) {
            float4 a = *(const float4*)&As[kk][ty * 4];
            float4 b = *(const float4*)&Bs[kk][tx * 4];
            float av[4] = {a.x, a.y, a.z, a.w};
            float bv[4] = {b.x, b.y, b.z, b.w};
#pragma unroll
            for (int i = 0; i < 4; i++)
#pragma unroll
                for (int j = 0; j < 4; j++) acc[i][j] += av[i] * bv[j];
        }
        __syncthreads();
    }
#pragma unroll
    for (int i = 0; i < 4; i++) {
        int r = bm + ty * 4 + i;
        if (r >= M) continue;
#pragma unroll
        for (int j = 0; j < 4; j++) {
            int cc = bn + tx * 4 + j;
            if (cc >= NC) continue;
            C[(long long)r * ldc + cc] = acc[i][j] + (bias ? bias[cc] : 0.f);
        }
    }
}

// ---------------- fp16 tensor-core GEMM (layer 3 output) ----------------
// C[M,121] = A[M,280] @ Wh[288,128] (padded, zeros beyond K=280/N=121), + bias.
// Block: 128(M) x 128(N), 8 warps 4x2, warp tile 32x64, m16n16k16 frags.
__global__ __launch_bounds__(256) void k_gemm_h16(
    const float* __restrict__ A, int lda, const __half* __restrict__ Bh,
    float* __restrict__ C, int ldc, int M, int K,
    const float* __restrict__ bias) {
    __shared__ __align__(16) __half As[128][40];   // K-chunk 32 (+pad to 40)
    __shared__ __align__(16) __half Bs[32][136];
    __shared__ __align__(16) float stg[8][16][20];
    int bm = blockIdx.x * 128;
    int tid = threadIdx.x;
    int wid = tid >> 5, lane = tid & 31;
    int wm = wid >> 1, wn = wid & 1;            // 4 x 2 warp grid

    wmma::fragment<wmma::accumulator, 16, 16, 16, float> acc[2][4];
#pragma unroll
    for (int i = 0; i < 2; i++)
#pragma unroll
        for (int j = 0; j < 4; j++) wmma::fill_fragment(acc[i][j], 0.f);

    for (int k0 = 0; k0 < 288; k0 += 32) {
        // A: 128x32 fp32 -> half (guarded; K=280 real)
#pragma unroll
        for (int i = tid; i < 128 * 32; i += 256) {
            int m = i >> 5, kk = i & 31;
            int gm = bm + m, gk = k0 + kk;
            As[m][kk] = __float2half((gm < M && gk < K) ? A[(long long)gm * lda + gk] : 0.f);
        }
        // B: 32x128 half, fully padded -> no guards
#pragma unroll
        for (int i = tid; i < 32 * 128; i += 256) {
            int kk = i >> 7, nn = i & 127;
            Bs[kk][nn] = Bh[(k0 + kk) * 128 + nn];
        }
        __syncthreads();
#pragma unroll
        for (int ks = 0; ks < 32; ks += 16) {
            wmma::fragment<wmma::matrix_a, 16, 16, 16, __half, wmma::row_major> fa[2];
            wmma::load_matrix_sync(fa[0], &As[wm * 32][ks], 40);
            wmma::load_matrix_sync(fa[1], &As[wm * 32 + 16][ks], 40);
#pragma unroll
            for (int j = 0; j < 4; j++) {
                wmma::fragment<wmma::matrix_b, 16, 16, 16, __half, wmma::row_major> fb;
                wmma::load_matrix_sync(fb, &Bs[ks][wn * 64 + j * 16], 136);
                wmma::mma_sync(acc[0][j], fa[0], fb, acc[0][j]);
                wmma::mma_sync(acc[1][j], fa[1], fb, acc[1][j]);
            }
        }
        __syncthreads();
    }

    // staged epilogue: bias + bounds (per-warp private staging)
#pragma unroll
    for (int i = 0; i < 2; i++)
#pragma unroll
        for (int j = 0; j < 4; j++) {
            wmma::store_matrix_sync(&stg[wid][0][0], acc[i][j], 20, wmma::mem_row_major);
            __syncwarp();
            int rb = bm + wm * 32 + i * 16;
            int cb = wn * 64 + j * 16;
            for (int t = lane; t < 256; t += 32) {
                int r = t >> 4, c = t & 15;
                int gr = rb + r, gc = cb + c;
                if (gr < M && gc < 121)
                    C[(long long)gr * ldc + gc] = stg[wid][r][c] + bias[gc];
            }
            __syncwarp();
        }
}

// ---------------- fused aggregation layers 1/2 (exp inline, no ew) ----------------
__global__ __launch_bounds__(256) void k_agg12(
    const int* __restrict__ ptr, const int* __restrict__ cnt,
    const int* __restrict__ csrc, const float* __restrict__ xw,
    const float* __restrict__ bias,
    float* __restrict__ hout, float* __restrict__ zout, int n) {
    int t = blockIdx.x * blockDim.x + threadIdx.x;
    if (t >= n * 10) return;
    int node = t / 10, g = t - node * 10;
    int c0 = g * 4;
    int hlo = c0 / 10, hhi = (c0 + 3) / 10;
    bool two = (hhi != hlo);
    int hj1 = (c0 + 1) / 10, hj2 = (c0 + 2) / 10;

    const float* rowd = xw + (long long)node * 88;
    float adlo = rowd[84 + hlo];
    float adhi = two ? rowd[84 + hhi] : adlo;
    // self loop
    float wlo = __expf(lrelu(rowd[80 + hlo] + adlo));
    float whi = two ? __expf(lrelu(rowd[80 + hhi] + adhi)) : wlo;
    float4 fs = *(const float4*)(rowd + c0);
    float w1 = (hj1 == hlo) ? wlo : whi, w2 = (hj2 == hlo) ? wlo : whi;
    float ax = fs.x * wlo, ay = fs.y * w1, az = fs.z * w2, aw = fs.w * whi;
    float dlo = wlo, dhi = whi;

    int st = ptr[node], deg = cnt[node];
    for (int k = 0; k < deg; k++) {
        int s = csrc[st + k];
        const float* rows = xw + (long long)s * 88;
        float wl = __expf(lrelu(rows[80 + hlo] + adlo));
        float wh = two ? __expf(lrelu(rows[80 + hhi] + adhi)) : wl;
        float4 f = *(const float4*)(rows + c0);
        ax += f.x * wl;
        ay += f.y * ((hj1 == hlo) ? wl : wh);
        az += f.z * ((hj2 == hlo) ? wl : wh);
        aw += f.w * wh;
        dlo += wl;
        dhi += wh;
    }
    float ilo = 1.f / dlo, ihi = two ? (1.f / dhi) : ilo;
    float i1 = (hj1 == hlo) ? ilo : ihi, i2 = (hj2 == hlo) ? ilo : ihi;
    float4 r;
    r.x = ax * ilo + rowd[40 + c0 + 0] + bias[c0 + 0];
    r.y = ay * i1  + rowd[40 + c0 + 1] + bias[c0 + 1];
    r.z = az * i2  + rowd[40 + c0 + 2] + bias[c0 + 2];
    r.w = aw * ihi + rowd[40 + c0 + 3] + bias[c0 + 3];
    r.x = r.x > 0.f ? r.x : (__expf(r.x) - 1.f);
    r.y = r.y > 0.f ? r.y : (__expf(r.y) - 1.f);
    r.z = r.z > 0.f ? r.z : (__expf(r.z) - 1.f);
    r.w = r.w > 0.f ? r.w : (__expf(r.w) - 1.f);
    *(float4*)(hout + (long long)node * 40 + c0) = r;
    if (zout) *(float4*)(zout + (long long)node * 280 + 240 + c0) = r;
}

// ---------------- layer 3 ----------------
__global__ void k_asrc3(const float* __restrict__ h2, const float* __restrict__ vs,
                        const float* __restrict__ vd, float* as_, float* ad_, int n) {
    int t = blockIdx.x * blockDim.x + threadIdx.x;
    if (t >= n * 12) return;
    int node = t / 12, j = t - node * 12;
    const float* v = (j < 6) ? &vs[j * 40] : &vd[(j - 6) * 40];
    const float* hr = &h2[(long long)node * 40];
    float a = 0.f;
#pragma unroll
    for (int k = 0; k < 40; k++) a += hr[k] * v[k];
    if (j < 6) as_[node * 6 + j] = a;
    else ad_[node * 6 + (j - 6)] = a;
}

__global__ void k_selfw(const float* __restrict__ as_, const float* __restrict__ ad_,
                        float* ws, int n) {
    int t = blockIdx.x * blockDim.x + threadIdx.x;
    if (t >= n * 6) return;
    ws[t] = __expf(lrelu(as_[t] + ad_[t]));
}

__global__ void k_exp3(const int* __restrict__ csrc, const int* __restrict__ cdst,
                       const float* __restrict__ as_, const float* __restrict__ ad_,
                       float* __restrict__ ew, int E) {
    long long t = (long long)blockIdx.x * blockDim.x + threadIdx.x;
    if (t >= (long long)E * 6) return;
    int slot = (int)(t / 6), h = (int)(t - (long long)slot * 6);
    int s = csrc[slot], d = cdst[slot];
    float sc = lrelu(as_[s * 6 + h] + ad_[d * 6 + h]);
    ew[t] = __expf(sc);
}

__global__ __launch_bounds__(256) void k_agg3(
    const int* __restrict__ ptr, const int* __restrict__ cnt,
    const int* __restrict__ csrc, const float* __restrict__ h2,
    const float* __restrict__ ew, const float* __restrict__ ws,
    float* __restrict__ z, int n) {
    int t = blockIdx.x * blockDim.x + threadIdx.x;
    if (t >= n * 10) return;
    int node = t / 10, g = t - node * 10;
    int fc0 = g * 4;

    float den[6];
    float4 acc[6];
    float4 fself = *(const float4*)(h2 + (long long)node * 40 + fc0);
#pragma unroll
    for (int h = 0; h < 6; h++) {
        float w = ws[node * 6 + h];
        den[h] = w;
        acc[h].x = fself.x * w; acc[h].y = fself.y * w;
        acc[h].z = fself.z * w; acc[h].w = fself.w * w;
    }
    int st = ptr[node], deg = cnt[node];
    for (int k = 0; k < deg; k++) {
        int slot = st + k;
        int s = csrc[slot];
        float4 f = *(const float4*)(h2 + (long long)s * 40 + fc0);
        const float* wp = &ew[(long long)slot * 6];
#pragma unroll
        for (int h = 0; h < 6; h++) {
            float w = wp[h];
            den[h] += w;
            acc[h].x += f.x * w; acc[h].y += f.y * w;
            acc[h].z += f.z * w; acc[h].w += f.w * w;
        }
    }
#pragma unroll
    for (int h = 0; h < 6; h++) {
        float sc = 1.f / (6.f * den[h]);
        float4 r;
        r.x = acc[h].x * sc; r.y = acc[h].y * sc;
        r.z = acc[h].z * sc; r.w = acc[h].w * sc;
        *(float4*)(z + (long long)node * 280 + h * 40 + fc0) = r;
    }
}

// ---------------- host ----------------
extern "C" void kernel_launch(void* const* d_in, const int* in_sizes, int n_in,
                              void* d_out, int out_size) {
    const float* x   = (const float*)d_in[0];
    const int*   ei  = (const int*)d_in[1];
    const float* W1  = (const float*)d_in[2];
    const float* as1 = (const float*)d_in[3];
    const float* ad1 = (const float*)d_in[4];
    const float* b1  = (const float*)d_in[5];
    const float* lw1 = (const float*)d_in[6];
    const float* lb1 = (const float*)d_in[7];
    const float* W2  = (const float*)d_in[8];
    const float* as2 = (const float*)d_in[9];
    const float* ad2 = (const float*)d_in[10];
    const float* b2  = (const float*)d_in[11];
    const float* lw2 = (const float*)d_in[12];
    const float* lb2 = (const float*)d_in[13];
    const float* W3  = (const float*)d_in[14];
    const float* as3 = (const float*)d_in[15];
    const float* ad3 = (const float*)d_in[16];
    const float* b3  = (const float*)d_in[17];
    const float* lw3 = (const float*)d_in[18];
    const float* lb3 = (const float*)d_in[19];
    float* out = (float*)d_out;

    int E = in_sizes[1] / 2;
    int n = in_sizes[0] / 50;
    const int* src = ei;
    const int* dst = ei + E;

    float *xw, *h, *z, *asrc, *adst, *ws, *ew;
    float *w1e, *w2e, *bc1, *bc2, *bc3, *vs3, *vd3;
    __half* w3h;
    int *cnt, *ptr, *cur, *bsum, *csrc, *cdst;
    cudaGetSymbolAddress((void**)&xw, g_xw);
    cudaGetSymbolAddress((void**)&h, g_h);
    cudaGetSymbolAddress((void**)&z, g_z);
    cudaGetSymbolAddress((void**)&asrc, g_asrc);
    cudaGetSymbolAddress((void**)&adst, g_adst);
    cudaGetSymbolAddress((void**)&ws, g_ws);
    cudaGetSymbolAddress((void**)&ew, g_ew);
    cudaGetSymbolAddress((void**)&cnt, g_cnt);
    cudaGetSymbolAddress((void**)&ptr, g_ptr);
    cudaGetSymbolAddress((void**)&cur, g_cur);
    cudaGetSymbolAddress((void**)&bsum, g_bsum);
    cudaGetSymbolAddress((void**)&csrc, g_csrc);
    cudaGetSymbolAddress((void**)&cdst, g_cdst);
    cudaGetSymbolAddress((void**)&w1e, g_w1e);
    cudaGetSymbolAddress((void**)&w2e, g_w2e);
    cudaGetSymbolAddress((void**)&w3h, g_w3h);
    cudaGetSymbolAddress((void**)&bc1, g_bc1);
    cudaGetSymbolAddress((void**)&bc2, g_bc2);
    cudaGetSymbolAddress((void**)&bc3, g_bc3);
    cudaGetSymbolAddress((void**)&vs3, g_vs3);
    cudaGetSymbolAddress((void**)&vd3, g_vd3);

    // weight repack
    k_repack12<<<cdiv(50 * 88, TPB), TPB>>>(W1, lw1, as1, ad1, b1, lb1, w1e, bc1, 50);
    k_repack12<<<cdiv(40 * 88, TPB), TPB>>>(W2, lw2, as2, ad2, b2, lb2, w2e, bc2, 40);
    k_repack3h<<<cdiv(288 * 128, TPB), TPB>>>(W3, lw3, b3, lb3, w3h, bc3);
    k_vsd3<<<cdiv(480, TPB), TPB>>>(W3, as3, ad3, vs3, vd3);

    // CSR build (shared by all 3 layers)
    cudaMemsetAsync(cnt, 0, (size_t)n * sizeof(int));
    k_hist<<<cdiv(E, TPB), TPB>>>(dst, cnt, E);
    int nb = cdiv(n, 1024);
    k_scan1<<<nb, 1024>>>(cnt, ptr, bsum, n);
    k_scan2<<<1, 128>>>(bsum, nb);
    k_scan3<<<cdiv(n, TPB), TPB>>>(ptr, cur, bsum, n);
    k_scatter<<<cdiv(E, TPB), TPB>>>(src, dst, cur, csrc, cdst, E);

    // ---- layer 1 ----
    {
        dim3 g(cdiv(n, 64), cdiv(88, 64));
        k_gemm<<<g, 256>>>(x, 50, w1e, 88, xw, 88, n, 50, 88, nullptr);
        k_agg12<<<cdiv(n * 10, TPB), TPB>>>(ptr, cnt, csrc, xw, bc1, h, nullptr, n);
    }
    // ---- layer 2 ----
    {
        dim3 g(cdiv(n, 64), cdiv(88, 64));
        k_gemm<<<g, 256>>>(h, 40, w2e, 88, xw, 88, n, 40, 88, nullptr);
        k_agg12<<<cdiv(n * 10, TPB), TPB>>>(ptr, cnt, csrc, xw, bc2, h, z, n);
    }
    // ---- layer 3 ----
    {
        k_asrc3<<<cdiv(n * 12, TPB), TPB>>>(h, vs3, vd3, asrc, adst, n);
        k_selfw<<<cdiv(n * 6, TPB), TPB>>>(asrc, adst, ws, n);
        k_exp3<<<cdiv((long long)E * 6, TPB), TPB>>>(csrc, cdst, asrc, adst, ew, E);
        k_agg3<<<cdiv(n * 10, TPB), TPB>>>(ptr, cnt, csrc, h, ew, ws, z, n);
        k_gemm_h16<<<cdiv(n, 128), 256>>>(z, 280, w3h, out, 121, n, 280, bc3);
    }
}

// round 8
// speedup vs baseline: 3.7939x; 1.1562x over previous
#include <cuda_runtime.h>
#include <cuda_fp16.h>
#include <mma.h>
using namespace nvcuda;

#define NN 100000
#define EE 1600000
#define TPB 256

static inline int cdiv(long long a, int b) { return (int)((a + b - 1) / b); }

// ---------------- device scratch ----------------
__device__ __align__(16) float g_xw[(size_t)NN * 88];   // [xw(40) | skip(40) | asrc(4) | adst(4)]
__device__ __align__(16) float g_h[(size_t)NN * 40];
__device__ __align__(16) __half g_hh[(size_t)NN * 40];  // fp16 copy of h2 for layer3 gathers
__device__ __align__(16) float g_z[(size_t)NN * 280];   // z(240) | h2 skip(40)
__device__ float g_asrc[(size_t)NN * 6];
__device__ float g_adst[(size_t)NN * 6];
__device__ float g_ws[(size_t)NN * 6];                  // self-loop exp weights (layer3)
__device__ float g_ew[(size_t)EE * 6];                  // per-edge exp weights (layer3, CSR order)
__device__ int g_cnt[NN], g_ptr[NN], g_cur[NN], g_bsum[128];
__device__ int g_csrc[EE];
__device__ float g_w1e[50 * 88];
__device__ float g_w2e[40 * 88];
__device__ __align__(16) __half g_w3h[288 * 128];       // padded half weights for layer3 GEMM
__device__ float g_bc1[40], g_bc2[40], g_bc3[121];
__device__ float g_vs3[240], g_vd3[240];

__device__ __forceinline__ float lrelu(float x) { return x > 0.f ? x : 0.2f * x; }

// ---------------- weight repack ----------------
__global__ void k_repack12(const float* __restrict__ W, const float* __restrict__ lw,
                           const float* __restrict__ as_, const float* __restrict__ ad_,
                           const float* __restrict__ b, const float* __restrict__ lb,
                           float* we, float* bc, int K) {
    int t = blockIdx.x * blockDim.x + threadIdx.x;
    if (t >= K * 88) return;
    int k = t / 88, j = t % 88;
    float v;
    if (j < 40) v = W[k * 40 + j];
    else if (j < 80) v = lw[k * 40 + (j - 40)];
    else if (j < 84) {
        int h = j - 80; float a = 0.f;
        for (int d = 0; d < 10; d++) a += W[k * 40 + h * 10 + d] * as_[h * 10 + d];
        v = a;
    } else {
        int h = j - 84; float a = 0.f;
        for (int d = 0; d < 10; d++) a += W[k * 40 + h * 10 + d] * ad_[h * 10 + d];
        v = a;
    }
    we[t] = v;
    if (k == 0 && j < 40) bc[j] = b[j] + lb[j];
}

// layer3 weights -> half, padded to [288][128] (rows 240..279 = lw3, rest zero)
__global__ void k_repack3h(const float* __restrict__ W3, const float* __restrict__ lw3,
                           const float* __restrict__ b3, const float* __restrict__ lb3,
                           __half* wh, float* bc) {
    int t = blockIdx.x * blockDim.x + threadIdx.x;
    if (t >= 288 * 128) return;
    int r = t >> 7, c = t & 127;
    float v = 0.f;
    if (c < 121) {
        if (r < 240) { int h = r / 40, k = r % 40; v = W3[k * 726 + h * 121 + c]; }
        else if (r < 280) v = lw3[(r - 240) * 121 + c];
    }
    wh[t] = __float2half(v);
    if (r == 0 && c < 121) bc[c] = b3[c] + lb3[c];
}

// folded attention vectors, warp per output
__global__ void k_vsd3(const float* __restrict__ W3, const float* __restrict__ as3,
                       const float* __restrict__ ad3, float* vs, float* vd) {
    int w = (blockIdx.x * blockDim.x + threadIdx.x) >> 5;
    int lane = threadIdx.x & 31;
    if (w >= 480) return;
    int side = w / 240, idx = w % 240, h = idx / 40, k = idx % 40;
    const float* att = side ? ad3 : as3;
    float a = 0.f;
    for (int c = lane; c < 121; c += 32) a += W3[k * 726 + h * 121 + c] * att[h * 121 + c];
#pragma unroll
    for (int o = 16; o; o >>= 1) a += __shfl_down_sync(0xffffffffu, a, o);
    if (lane == 0) (side ? vd : vs)[idx] = a;
}

// ---------------- CSR build ----------------
__global__ void k_hist(const int* __restrict__ dst, int* cnt, int E) {
    int t = blockIdx.x * blockDim.x + threadIdx.x;
    if (t < E) atomicAdd(&cnt[dst[t]], 1);
}

__global__ void k_scan1(const int* __restrict__ cnt, int* ptr, int* bsum, int n) {
    __shared__ int sh[1024];
    int i = blockIdx.x * 1024 + threadIdx.x;
    int v = (i < n) ? cnt[i] : 0;
    sh[threadIdx.x] = v;
    __syncthreads();
    for (int off = 1; off < 1024; off <<= 1) {
        int t = (threadIdx.x >= off) ? sh[threadIdx.x - off] : 0;
        __syncthreads();
        sh[threadIdx.x] += t;
        __syncthreads();
    }
    if (i < n) ptr[i] = sh[threadIdx.x] - v;   // exclusive
    if (threadIdx.x == 1023) bsum[blockIdx.x] = sh[1023];
}

__global__ void k_scan2(int* bsum, int nb) {
    __shared__ int sh[128];
    int v = (threadIdx.x < nb) ? bsum[threadIdx.x] : 0;
    sh[threadIdx.x] = v;
    __syncthreads();
    for (int off = 1; off < 128; off <<= 1) {
        int t = (threadIdx.x >= off) ? sh[threadIdx.x - off] : 0;
        __syncthreads();
        sh[threadIdx.x] += t;
        __syncthreads();
    }
    if (threadIdx.x < nb) bsum[threadIdx.x] = sh[threadIdx.x] - v;
}

__global__ void k_scan3(int* ptr, int* cur, const int* __restrict__ bsum, int n) {
    int i = blockIdx.x * blockDim.x + threadIdx.x;
    if (i >= n) return;
    int p = ptr[i] + bsum[i >> 10];
    ptr[i] = p;
    cur[i] = p;
}

__global__ void k_scatter(const int* __restrict__ src, const int* __restrict__ dst,
                          int* cur, int* csrc, int E) {
    int t = blockIdx.x * blockDim.x + threadIdx.x;
    if (t >= E) return;
    int slot = atomicAdd(&cur[dst[t]], 1);
    csrc[slot] = src[t];
}

// ---------------- SIMT fp32 GEMM, 64(M) x 96(N) tile (layers 1/2, NC<=96) ----------------
__global__ __launch_bounds__(256) void k_gemm96(const float* __restrict__ A, int lda,
                                                const float* __restrict__ B,
                                                float* __restrict__ C,
                                                int M, int K, int NC) {
    __shared__ __align__(16) float As[16][68];
    __shared__ __align__(16) float Bs[16][100];
    int bm = blockIdx.x * 64;
    int tid = threadIdx.x;
    int tx = tid & 15, ty = tid >> 4;
    float acc[4][6] = {};
    for (int k0 = 0; k0 < K; k0 += 16) {
#pragma unroll
        for (int i = tid; i < 64 * 16; i += 256) {
            int m = i >> 4, kk = i & 15;
            int gm = bm + m, gk = k0 + kk;
            As[kk][m] = (gm < M && gk < K) ? A[(long long)gm * lda + gk] : 0.f;
        }
#pragma unroll
        for (int i = tid; i < 16 * 96; i += 256) {
            int kk = i / 96, nn = i - kk * 96;
            int gk = k0 + kk;
            Bs[kk][nn] = (gk < K && nn < NC) ? B[gk * NC + nn] : 0.f;
        }
        __syncthreads();
#pragma unroll
        for (int kk = 0; kk < 16; kk++) {
            float a[4], b[6];
#pragma unroll
            for (int i = 0; i < 4; i++) a[i] = As[kk][ty * 4 + i];
#pragma unroll
            for (int j = 0; j < 6; j++) b[j] = Bs[kk][tx * 6 + j];
#pragma unroll
            for (int i = 0; i < 4; i++)
#pragma unroll
                for (int j = 0; j < 6; j++) acc[i][j] += a[i] * b[j];
        }
        __syncthreads();
    }
#pragma unroll
    for (int i = 0; i < 4; i++) {
        int r = bm + ty * 4 + i;
        if (r >= M) continue;
#pragma unroll
        for (int j = 0; j < 6; j++) {
            int cc = tx * 6 + j;
            if (cc < NC) C[(long long)r * NC + cc] = acc[i][j];
        }
    }
}

// ---------------- fp16 tensor-core GEMM (layer 3 output) ----------------
__global__ __launch_bounds__(256) void k_gemm_h16(
    const float* __restrict__ A, int lda, const __half* __restrict__ Bh,
    float* __restrict__ C, int ldc, int M, int K,
    const float* __restrict__ bias) {
    __shared__ __align__(16) __half As[128][40];   // K-chunk 32 (+pad to 40)
    __shared__ __align__(16) __half Bs[32][136];
    __shared__ __align__(16) float stg[8][16][20];
    int bm = blockIdx.x * 128;
    int tid = threadIdx.x;
    int wid = tid >> 5, lane = tid & 31;
    int wm = wid >> 1, wn = wid & 1;            // 4 x 2 warp grid

    wmma::fragment<wmma::accumulator, 16, 16, 16, float> acc[2][4];
#pragma unroll
    for (int i = 0; i < 2; i++)
#pragma unroll
        for (int j = 0; j < 4; j++) wmma::fill_fragment(acc[i][j], 0.f);

    for (int k0 = 0; k0 < 288; k0 += 32) {
#pragma unroll
        for (int i = tid; i < 128 * 32; i += 256) {
            int m = i >> 5, kk = i & 31;
            int gm = bm + m, gk = k0 + kk;
            As[m][kk] = __float2half((gm < M && gk < K) ? A[(long long)gm * lda + gk] : 0.f);
        }
#pragma unroll
        for (int i = tid; i < 32 * 128; i += 256) {
            int kk = i >> 7, nn = i & 127;
            Bs[kk][nn] = Bh[(k0 + kk) * 128 + nn];
        }
        __syncthreads();
#pragma unroll
        for (int ks = 0; ks < 32; ks += 16) {
            wmma::fragment<wmma::matrix_a, 16, 16, 16, __half, wmma::row_major> fa[2];
            wmma::load_matrix_sync(fa[0], &As[wm * 32][ks], 40);
            wmma::load_matrix_sync(fa[1], &As[wm * 32 + 16][ks], 40);
#pragma unroll
            for (int j = 0; j < 4; j++) {
                wmma::fragment<wmma::matrix_b, 16, 16, 16, __half, wmma::row_major> fb;
                wmma::load_matrix_sync(fb, &Bs[ks][wn * 64 + j * 16], 136);
                wmma::mma_sync(acc[0][j], fa[0], fb, acc[0][j]);
                wmma::mma_sync(acc[1][j], fa[1], fb, acc[1][j]);
            }
        }
        __syncthreads();
    }
#pragma unroll
    for (int i = 0; i < 2; i++)
#pragma unroll
        for (int j = 0; j < 4; j++) {
            wmma::store_matrix_sync(&stg[wid][0][0], acc[i][j], 20, wmma::mem_row_major);
            __syncwarp();
            int rb = bm + wm * 32 + i * 16;
            int cb = wn * 64 + j * 16;
            for (int t = lane; t < 256; t += 32) {
                int r = t >> 4, c = t & 15;
                int gr = rb + r, gc = cb + c;
                if (gr < M && gc < 121)
                    C[(long long)gr * ldc + gc] = stg[wid][r][c] + bias[gc];
            }
            __syncwarp();
        }
}

// ---------------- fused aggregation layers 1/2: thread = (node, head) ----------------
// 4 exps per edge (optimal), 10 cols per thread, no ew buffer, no atomics.
__global__ __launch_bounds__(256) void k_agg12(
    const int* __restrict__ ptr, const int* __restrict__ cnt,
    const int* __restrict__ csrc, const float* __restrict__ xw,
    const float* __restrict__ bias,
    float* __restrict__ hout, float* __restrict__ zout, __half* __restrict__ hh, int n) {
    int t = blockIdx.x * blockDim.x + threadIdx.x;
    if (t >= n * 4) return;
    int node = t >> 2, h = t & 3;
    const float* rowd = xw + (long long)node * 88;
    float adv = rowd[84 + h];
    float w = __expf(lrelu(rowd[80 + h] + adv));
    float den = w;
    float acc[10];
#pragma unroll
    for (int i = 0; i < 10; i++) acc[i] = w * rowd[h * 10 + i];

    int st = ptr[node], deg = cnt[node];
    for (int k = 0; k < deg; k++) {
        int s = csrc[st + k];
        const float* rows = xw + (long long)s * 88;
        float wl = __expf(lrelu(rows[80 + h] + adv));
        den += wl;
        const float2* rp = (const float2*)(rows + h * 10);
#pragma unroll
        for (int i = 0; i < 5; i++) {
            float2 f = rp[i];
            acc[2 * i]     += f.x * wl;
            acc[2 * i + 1] += f.y * wl;
        }
    }
    float inv = 1.f / den;
    float out[10];
#pragma unroll
    for (int i = 0; i < 10; i++) {
        float v = acc[i] * inv + rowd[40 + h * 10 + i] + bias[h * 10 + i];
        out[i] = v > 0.f ? v : (__expf(v) - 1.f);
    }
    float2* hp = (float2*)(hout + (long long)node * 40 + h * 10);
#pragma unroll
    for (int i = 0; i < 5; i++) hp[i] = make_float2(out[2 * i], out[2 * i + 1]);
    if (zout) {
        float2* zp = (float2*)(zout + (long long)node * 280 + 240 + h * 10);
#pragma unroll
        for (int i = 0; i < 5; i++) zp[i] = make_float2(out[2 * i], out[2 * i + 1]);
    }
    if (hh) {
        __half2* qp = (__half2*)(hh + (long long)node * 40 + h * 10);
#pragma unroll
        for (int i = 0; i < 5; i++) qp[i] = __floats2half2_rn(out[2 * i], out[2 * i + 1]);
    }
}

// ---------------- layer 3 ----------------
// per-node attention logits (both sides) + self-loop weight, fused
__global__ void k_att3(const float* __restrict__ h2, const float* __restrict__ vs,
                       const float* __restrict__ vd, float* as_, float* ad_,
                       float* ws, int n) {
    int t = blockIdx.x * blockDim.x + threadIdx.x;
    if (t >= n * 6) return;
    int node = t / 6, h = t - node * 6;
    const float* hr = &h2[(long long)node * 40];
    const float* v1 = &vs[h * 40];
    const float* v2 = &vd[h * 40];
    float a = 0.f, b = 0.f;
#pragma unroll
    for (int k = 0; k < 40; k++) { float x = hr[k]; a += x * v1[k]; b += x * v2[k]; }
    as_[t] = a;
    ad_[t] = b;
    ws[t] = __expf(lrelu(a + b));
}

// per-node edge exp weights (dst implicit; no cdst array)
__global__ void k_exp3(const int* __restrict__ ptr, const int* __restrict__ cnt,
                       const int* __restrict__ csrc,
                       const float* __restrict__ as_, const float* __restrict__ ad_,
                       float* __restrict__ ew, int n) {
    int t = blockIdx.x * blockDim.x + threadIdx.x;
    if (t >= n * 6) return;
    int node = t / 6, h = t - node * 6;
    float ad = ad_[t];
    int st = ptr[node], deg = cnt[node];
    for (int k = 0; k < deg; k++) {
        int slot = st + k;
        int s = csrc[slot];
        ew[(long long)slot * 6 + h] = __expf(lrelu(as_[s * 6 + h] + ad));
    }
}

// aggregation: thread = (node, 4 feature cols), 6 heads in registers; fp16 gathers
__global__ __launch_bounds__(256) void k_agg3(
    const int* __restrict__ ptr, const int* __restrict__ cnt,
    const int* __restrict__ csrc, const float* __restrict__ h2,
    const __half* __restrict__ hh, const float* __restrict__ ew,
    const float* __restrict__ ws, float* __restrict__ z, int n) {
    int t = blockIdx.x * blockDim.x + threadIdx.x;
    if (t >= n * 10) return;
    int node = t / 10, g = t - node * 10;
    int fc0 = g * 4;

    float den[6];
    float4 acc[6];
    float4 fself = *(const float4*)(h2 + (long long)node * 40 + fc0);
#pragma unroll
    for (int h = 0; h < 6; h++) {
        float w = ws[node * 6 + h];
        den[h] = w;
        acc[h].x = fself.x * w; acc[h].y = fself.y * w;
        acc[h].z = fself.z * w; acc[h].w = fself.w * w;
    }
    int st = ptr[node], deg = cnt[node];
    for (int k = 0; k < deg; k++) {
        int slot = st + k;
        int s = csrc[slot];
        uint2 raw = *(const uint2*)(hh + (long long)s * 40 + fc0);
        __half2 p0 = *reinterpret_cast<__half2*>(&raw.x);
        __half2 p1 = *reinterpret_cast<__half2*>(&raw.y);
        float2 f01 = __half22float2(p0);
        float2 f23 = __half22float2(p1);
        const float* wp = &ew[(long long)slot * 6];
#pragma unroll
        for (int h = 0; h < 6; h++) {
            float w = wp[h];
            den[h] += w;
            acc[h].x += f01.x * w; acc[h].y += f01.y * w;
            acc[h].z += f23.x * w; acc[h].w += f23.y * w;
        }
    }
#pragma unroll
    for (int h = 0; h < 6; h++) {
        float sc = 1.f / (6.f * den[h]);
        float4 r;
        r.x = acc[h].x * sc; r.y = acc[h].y * sc;
        r.z = acc[h].z * sc; r.w = acc[h].w * sc;
        *(float4*)(z + (long long)node * 280 + h * 40 + fc0) = r;
    }
}

// ---------------- host ----------------
extern "C" void kernel_launch(void* const* d_in, const int* in_sizes, int n_in,
                              void* d_out, int out_size) {
    const float* x   = (const float*)d_in[0];
    const int*   ei  = (const int*)d_in[1];
    const float* W1  = (const float*)d_in[2];
    const float* as1 = (const float*)d_in[3];
    const float* ad1 = (const float*)d_in[4];
    const float* b1  = (const float*)d_in[5];
    const float* lw1 = (const float*)d_in[6];
    const float* lb1 = (const float*)d_in[7];
    const float* W2  = (const float*)d_in[8];
    const float* as2 = (const float*)d_in[9];
    const float* ad2 = (const float*)d_in[10];
    const float* b2  = (const float*)d_in[11];
    const float* lw2 = (const float*)d_in[12];
    const float* lb2 = (const float*)d_in[13];
    const float* W3  = (const float*)d_in[14];
    const float* as3 = (const float*)d_in[15];
    const float* ad3 = (const float*)d_in[16];
    const float* b3  = (const float*)d_in[17];
    const float* lw3 = (const float*)d_in[18];
    const float* lb3 = (const float*)d_in[19];
    float* out = (float*)d_out;

    int E = in_sizes[1] / 2;
    int n = in_sizes[0] / 50;
    const int* src = ei;
    const int* dst = ei + E;

    float *xw, *h, *z, *asrc, *adst, *ws, *ew;
    float *w1e, *w2e, *bc1, *bc2, *bc3, *vs3, *vd3;
    __half *w3h, *hh;
    int *cnt, *ptr, *cur, *bsum, *csrc;
    cudaGetSymbolAddress((void**)&xw, g_xw);
    cudaGetSymbolAddress((void**)&h, g_h);
    cudaGetSymbolAddress((void**)&hh, g_hh);
    cudaGetSymbolAddress((void**)&z, g_z);
    cudaGetSymbolAddress((void**)&asrc, g_asrc);
    cudaGetSymbolAddress((void**)&adst, g_adst);
    cudaGetSymbolAddress((void**)&ws, g_ws);
    cudaGetSymbolAddress((void**)&ew, g_ew);
    cudaGetSymbolAddress((void**)&cnt, g_cnt);
    cudaGetSymbolAddress((void**)&ptr, g_ptr);
    cudaGetSymbolAddress((void**)&cur, g_cur);
    cudaGetSymbolAddress((void**)&bsum, g_bsum);
    cudaGetSymbolAddress((void**)&csrc, g_csrc);
    cudaGetSymbolAddress((void**)&w1e, g_w1e);
    cudaGetSymbolAddress((void**)&w2e, g_w2e);
    cudaGetSymbolAddress((void**)&w3h, g_w3h);
    cudaGetSymbolAddress((void**)&bc1, g_bc1);
    cudaGetSymbolAddress((void**)&bc2, g_bc2);
    cudaGetSymbolAddress((void**)&bc3, g_bc3);
    cudaGetSymbolAddress((void**)&vs3, g_vs3);
    cudaGetSymbolAddress((void**)&vd3, g_vd3);

    // weight repack
    k_repack12<<<cdiv(50 * 88, TPB), TPB>>>(W1, lw1, as1, ad1, b1, lb1, w1e, bc1, 50);
    k_repack12<<<cdiv(40 * 88, TPB), TPB>>>(W2, lw2, as2, ad2, b2, lb2, w2e, bc2, 40);
    k_repack3h<<<cdiv(288 * 128, TPB), TPB>>>(W3, lw3, b3, lb3, w3h, bc3);
    k_vsd3<<<60, TPB>>>(W3, as3, ad3, vs3, vd3);

    // CSR build (shared by all 3 layers)
    cudaMemsetAsync(cnt, 0, (size_t)n * sizeof(int));
    k_hist<<<cdiv(E, TPB), TPB>>>(dst, cnt, E);
    int nb = cdiv(n, 1024);
    k_scan1<<<nb, 1024>>>(cnt, ptr, bsum, n);
    k_scan2<<<1, 128>>>(bsum, nb);
    k_scan3<<<cdiv(n, TPB), TPB>>>(ptr, cur, bsum, n);
    k_scatter<<<cdiv(E, TPB), TPB>>>(src, dst, cur, csrc, E);

    // ---- layer 1 ----
    k_gemm96<<<cdiv(n, 64), 256>>>(x, 50, w1e, xw, n, 50, 88);
    k_agg12<<<cdiv(n * 4, TPB), TPB>>>(ptr, cnt, csrc, xw, bc1, h, nullptr, nullptr, n);

    // ---- layer 2 ----
    k_gemm96<<<cdiv(n, 64), 256>>>(h, 40, w2e, xw, n, 40, 88);
    k_agg12<<<cdiv(n * 4, TPB), TPB>>>(ptr, cnt, csrc, xw, bc2, h, z, hh, n);

    // ---- layer 3 ----
    k_att3<<<cdiv(n * 6, TPB), TPB>>>(h, vs3, vd3, asrc, adst, ws, n);
    k_exp3<<<cdiv(n * 6, TPB), TPB>>>(ptr, cnt, csrc, asrc, adst, ew, n);
    k_agg3<<<cdiv(n * 10, TPB), TPB>>>(ptr, cnt, csrc, h, hh, ew, ws, z, n);
    k_gemm_h16<<<cdiv(n, 128), 256>>>(z, 280, w3h, out, 121, n, 280, bc3);
}